// round 13
// baseline (speedup 1.0000x reference)
#include <cuda_runtime.h>
#include <cuda_fp16.h>
#include <math.h>
#include <stdint.h>

// ---------------------------------------------------------------------------
// WindowAttention (Swin): B_=256, N=98, DIM=768, NH=24, HD=32, NW=64
// Phase 1: QKV GEMM, mma.sync fp16. CTA 128x96 (one head), 4 warps (64x48),
//          2-stage cp.async, 3 CTAs/SM, smem-staged coalesced epilogue.
// Phase 2: tensor-core attention, 2 windows per CTA with cp.async prefetch,
//          per-head bias table (L2-resident) + mask loads.
// ---------------------------------------------------------------------------

#define B_    256
#define NTOK  98
#define DIMC  768
#define NHEAD 24
#define HD    32
#define NWIN  64
#define SCALE 0.17677669529663687f

#define GM (B_ * NTOK)     // 25088
#define GK DIMC            // 768
#define GN (3 * DIMC)      // 2304
#define NN (NTOK * NTOK)   // 9604

// Scratch
__device__ __half g_asp[(size_t)GM * GK];      // x fp16
__device__ __half g_bh[(size_t)GN * GK];       // w fp16
__device__ __half g_qh[B_ * NHEAD * NTOK * HD];
__device__ __half g_kh[B_ * NHEAD * NTOK * HD];
__device__ __half g_vh[B_ * NHEAD * NTOK * HD];
__device__ float  g_bias[NHEAD * NN];          // rel-pos bias [h][r][j]

// ---------------- helpers ---------------------------------------------------

__device__ __forceinline__ uint32_t smem_u32(const void* p) {
    uint32_t a;
    asm("{ .reg .u64 t; cvta.to.shared.u64 t, %1; cvt.u32.u64 %0, t; }" : "=r"(a) : "l"(p));
    return a;
}
#define CP16(dst, src) \
    asm volatile("cp.async.cg.shared.global [%0], [%1], 16;" :: "r"(dst), "l"(src) : "memory")
#define CP_COMMIT() asm volatile("cp.async.commit_group;" ::: "memory")
#define CP_WAIT(n)  asm volatile("cp.async.wait_group %0;" :: "n"(n) : "memory")

__device__ __forceinline__ void ldm_x4(uint32_t& r0, uint32_t& r1, uint32_t& r2,
                                       uint32_t& r3, uint32_t addr) {
    asm volatile("ldmatrix.sync.aligned.m8n8.x4.shared.b16 {%0,%1,%2,%3}, [%4];"
                 : "=r"(r0), "=r"(r1), "=r"(r2), "=r"(r3) : "r"(addr));
}
__device__ __forceinline__ void ldm_x4_t(uint32_t& r0, uint32_t& r1, uint32_t& r2,
                                         uint32_t& r3, uint32_t addr) {
    asm volatile("ldmatrix.sync.aligned.m8n8.x4.trans.shared.b16 {%0,%1,%2,%3}, [%4];"
                 : "=r"(r0), "=r"(r1), "=r"(r2), "=r"(r3) : "r"(addr));
}
__device__ __forceinline__ void mma_f16(float* c, const uint32_t* a, uint32_t b0, uint32_t b1) {
    asm volatile(
        "mma.sync.aligned.m16n8k16.row.col.f32.f16.f16.f32 "
        "{%0,%1,%2,%3}, {%4,%5,%6,%7}, {%8,%9}, {%0,%1,%2,%3};"
        : "+f"(c[0]), "+f"(c[1]), "+f"(c[2]), "+f"(c[3])
        : "r"(a[0]), "r"(a[1]), "r"(a[2]), "r"(a[3]), "r"(b0), "r"(b1));
}

// ---------------- fused prep kernel -----------------------------------------
// Range 1: x -> fp16. Range 2: w -> fp16. Range 3: per-head bias gather.

#define NA4 ((GM * GK) / 4)
#define NB4 ((GN * GK) / 4)
#define NC4 ((NHEAD * NN) / 4)
#define NTOT4 (NA4 + NB4 + NC4)

__global__ __launch_bounds__(256) void prep_all(
    const float* __restrict__ x, const float* __restrict__ w,
    const float* __restrict__ rel_table, const int* __restrict__ rel_index)
{
    int i = blockIdx.x * 256 + threadIdx.x;
    if (i < NA4) {
        float4 v = *(const float4*)(x + (size_t)i * 4);
        __half2* dst = (__half2*)(g_asp + (size_t)i * 4);
        dst[0] = __floats2half2_rn(v.x, v.y);
        dst[1] = __floats2half2_rn(v.z, v.w);
    } else if (i < NA4 + NB4) {
        int j = i - NA4;
        float4 v = *(const float4*)(w + (size_t)j * 4);
        __half2* dst = (__half2*)(g_bh + (size_t)j * 4);
        dst[0] = __floats2half2_rn(v.x, v.y);
        dst[1] = __floats2half2_rn(v.z, v.w);
    } else if (i < NTOT4) {
        int q  = (i - NA4 - NB4) * 4;
        int h  = q / NN;
        int rj = q - h * NN;
        int4 id = *(const int4*)(rel_index + rj);
        float4 o;
        o.x = __ldg(rel_table + id.x * NHEAD + h);
        o.y = __ldg(rel_table + id.y * NHEAD + h);
        o.z = __ldg(rel_table + id.z * NHEAD + h);
        o.w = __ldg(rel_table + id.w * NHEAD + h);
        *(float4*)(g_bias + q) = o;
    }
}

// ---------------- QKV GEMM (mma.sync fp16) ----------------------------------
// BM=128, BN=96, BK=64. 4 warps (2m x 2n), warp tile 64x48.
// 2-stage cp.async, K=768 (12 chunks). Smem rows 128B, (kc ^ row&7) swizzle.

#define NSTAGE 2
#define CHUNKS 12
#define A_BYTES 16384
#define B96_BYTES 12288
#define STAGE_BYTES (A_BYTES + B96_BYTES)        // 28KB
#define SMEM_TOTAL (NSTAGE * STAGE_BYTES)        // 56KB
#define EP_PAD 104

__global__ __launch_bounds__(128, 3) void qkv_mma(const float* __restrict__ bias)
{
    extern __shared__ __align__(128) char smem[];
    const uint32_t sb = smem_u32(smem);

    const int tid  = threadIdx.x;
    const int lane = tid & 31;
    const int wid  = tid >> 5;
    const int wm   = wid & 1;
    const int wn   = wid >> 1;

    const int m0 = blockIdx.y * 128;
    const int h0 = blockIdx.x;

    const __half* agbase = g_asp + (size_t)m0 * GK;
    const __half* bgbase = g_bh + (size_t)(h0 * 96) * GK;

    const int sub  = lane >> 3;
    const int lr   = (lane & 7) + ((sub & 1) << 3);
    const int subh = sub >> 1;

    uint32_t a_rowoff[4];
    int      a_rx[4];
#pragma unroll
    for (int i = 0; i < 4; i++) {
        int row = wm * 64 + i * 16 + lr;
        a_rowoff[i] = (uint32_t)row * 128;
        a_rx[i]     = row & 7;
    }
    uint32_t b_rowoff[3];
    int      b_rx[3];
#pragma unroll
    for (int g = 0; g < 3; g++) {
        int row = wn * 48 + g * 16 + lr;
        b_rowoff[g] = (uint32_t)row * 128;
        b_rx[g]     = row & 7;
    }

    float acc[4][6][4];
#pragma unroll
    for (int i = 0; i < 4; i++)
#pragma unroll
        for (int j = 0; j < 6; j++)
#pragma unroll
            for (int q = 0; q < 4; q++) acc[i][j][q] = 0.0f;

    {
        uint32_t aB = sb;
        uint32_t bB = sb + A_BYTES;
#pragma unroll
        for (int l = 0; l < 8; l++) {
            int ci = tid + l * 128;
            int r = ci >> 3, kc = ci & 7;
            CP16(aB + r * 128 + ((kc ^ (r & 7)) << 4),
                 agbase + (size_t)r * GK + kc * 8);
        }
#pragma unroll
        for (int l = 0; l < 6; l++) {
            int ci = tid + l * 128;
            int r = ci >> 3, kc = ci & 7;
            CP16(bB + r * 128 + ((kc ^ (r & 7)) << 4),
                 bgbase + (size_t)r * GK + kc * 8);
        }
        CP_COMMIT();
    }

#pragma unroll 1
    for (int c = 0; c < CHUNKS; c++) {
        if (c + 1 < CHUNKS) {
            int cs = c + 1;
            uint32_t aB = sb + (cs & 1) * STAGE_BYTES;
            uint32_t bB = aB + A_BYTES;
#pragma unroll
            for (int l = 0; l < 8; l++) {
                int ci = tid + l * 128;
                int r = ci >> 3, kc = ci & 7;
                CP16(aB + r * 128 + ((kc ^ (r & 7)) << 4),
                     agbase + (size_t)r * GK + cs * 64 + kc * 8);
            }
#pragma unroll
            for (int l = 0; l < 6; l++) {
                int ci = tid + l * 128;
                int r = ci >> 3, kc = ci & 7;
                CP16(bB + r * 128 + ((kc ^ (r & 7)) << 4),
                     bgbase + (size_t)r * GK + cs * 64 + kc * 8);
            }
            CP_COMMIT();
            CP_WAIT(1);
        } else {
            CP_WAIT(0);
        }
        __syncthreads();

        const uint32_t aB = sb + (c & 1) * STAGE_BYTES;
        const uint32_t bB = aB + A_BYTES;

#pragma unroll
        for (int j = 0; j < 4; j++) {
            uint32_t af[4][4];
#pragma unroll
            for (int i = 0; i < 4; i++) {
                uint32_t addr = aB + a_rowoff[i]
                              + (uint32_t)(((j * 2 + subh) ^ a_rx[i]) << 4);
                ldm_x4(af[i][0], af[i][1], af[i][2], af[i][3], addr);
            }
            uint32_t bf[6][2];
#pragma unroll
            for (int g = 0; g < 3; g++) {
                uint32_t r0, r1, r2, r3;
                uint32_t addr = bB + b_rowoff[g]
                              + (uint32_t)(((j * 2 + subh) ^ b_rx[g]) << 4);
                ldm_x4(r0, r1, r2, r3, addr);
                bf[2 * g][0]     = r0; bf[2 * g][1]     = r2;
                bf[2 * g + 1][0] = r1; bf[2 * g + 1][1] = r3;
            }
#pragma unroll
            for (int i = 0; i < 4; i++)
#pragma unroll
                for (int n = 0; n < 6; n++)
                    mma_f16(acc[i][n], af[i], bf[n][0], bf[n][1]);
        }
        __syncthreads();
    }

    // ---- epilogue: smem transpose + coalesced stores ------------------------
    __half* ep = (__half*)smem;
    const int rbase = lane >> 2;
    const int cpair = lane & 3;
#pragma unroll
    for (int i = 0; i < 4; i++) {
#pragma unroll
        for (int half = 0; half < 2; half++) {
            int row = wm * 64 + i * 16 + rbase + half * 8;
#pragma unroll
            for (int n = 0; n < 6; n++) {
                int lc0 = wn * 48 + n * 8 + cpair * 2;
                float v0 = acc[i][n][half * 2]     + __ldg(&bias[h0 * 96 + lc0]);
                float v1 = acc[i][n][half * 2 + 1] + __ldg(&bias[h0 * 96 + lc0 + 1]);
                if (lc0 % 3 == 0)       v0 *= SCALE;
                if ((lc0 + 1) % 3 == 0) v1 *= SCALE;
                *(__half2*)&ep[row * EP_PAD + lc0] = __floats2half2_rn(v0, v1);
            }
        }
    }
    __syncthreads();

#pragma unroll
    for (int l = 0; l < 12; l++) {
        int ci    = tid + l * 128;
        int chunk = ci & 3;
        int rs    = ci >> 2;
        int row   = rs & 127;
        int s     = rs >> 7;
        int m   = m0 + row;
        int b   = m / NTOK;
        int tok = m - b * NTOK;
        size_t dst = ((size_t)b * NHEAD + h0) * NTOK * HD + (size_t)tok * HD
                   + chunk * 8;
        __half tmp[8];
#pragma unroll
        for (int d8 = 0; d8 < 8; d8++)
            tmp[d8] = ep[row * EP_PAD + s + 3 * (chunk * 8 + d8)];
        __half* base = (s == 0) ? g_qh : (s == 1) ? g_kh : g_vh;
        *(uint4*)(base + dst) = *(uint4*)tmp;
    }
}

// ---------------- tensor-core attention -------------------------------------
// CTA = (h, b-pair). 4 warps, 2 window buffers, cp.async prefetch overlap.

#define RSTR 40   // halfs per row (80 bytes)
#define WBUF (112 * RSTR)

__global__ __launch_bounds__(128) void attn_tc(
    const float* __restrict__ mask,
    float* __restrict__ out)
{
    __shared__ __align__(16) __half sQ[2][WBUF];
    __shared__ __align__(16) __half sK[2][WBUF];
    __shared__ __align__(16) __half sV[2][WBUF];

    const int h    = blockIdx.x;
    const int b0   = blockIdx.y * 2;
    const int tid  = threadIdx.x;
    const int lane = tid & 31;
    const int w    = tid >> 5;
    const int g    = lane >> 2;
    const int t    = lane & 3;

    // zero pad rows 98..111 of both buffers
    for (int idx = tid; idx < 14 * 4 * 2; idx += 128) {
        int bf  = idx >= 14 * 4;
        int ix  = idx - bf * 14 * 4;
        int row = 98 + (ix >> 2);
        int q   = ix & 3;
        uint4 z = {0, 0, 0, 0};
        *(uint4*)((char*)sQ[bf] + row * 80 + q * 16) = z;
        *(uint4*)((char*)sK[bf] + row * 80 + q * 16) = z;
        *(uint4*)((char*)sV[bf] + row * 80 + q * 16) = z;
    }

    // stage both windows (separate commit groups)
#pragma unroll
    for (int bf = 0; bf < 2; bf++) {
        const size_t gbase = ((size_t)(b0 + bf) * NHEAD + h) * NTOK * HD;
        const uint32_t qB = smem_u32(sQ[bf]);
        const uint32_t kB = smem_u32(sK[bf]);
        const uint32_t vB = smem_u32(sV[bf]);
        for (int idx = tid; idx < 98 * 4; idx += 128) {
            int row = idx >> 2;
            int q   = idx & 3;
            size_t src = gbase + row * 32 + q * 8;
            uint32_t doff = row * 80 + q * 16;
            CP16(qB + doff, g_qh + src);
            CP16(kB + doff, g_kh + src);
            CP16(vB + doff, g_vh + src);
        }
        CP_COMMIT();
    }

#pragma unroll 1
    for (int bf = 0; bf < 2; bf++) {
        if (bf == 0) { CP_WAIT(1); } else { CP_WAIT(0); }
        __syncthreads();

        const int b = b0 + bf;
        const uint32_t qhB = smem_u32(sQ[bf]);
        const uint32_t khB = smem_u32(sK[bf]);
        const uint32_t vhB = smem_u32(sV[bf]);
        const float* maskw = mask + (size_t)(b & (NWIN - 1)) * NN;
        const float* biash = g_bias + (size_t)h * NN;

#pragma unroll 1
        for (int mi = 0; mi < 2; mi++) {
            int mt = w + mi * 4;
            if (mt > 6) break;
            const int r0 = mt * 16;

            uint32_t qh[2][4];
            {
                int qrow = r0 + (lane & 7) + (((lane >> 3) & 1) << 3);
                int qcol = ((lane >> 4) << 3);
#pragma unroll
                for (int kt = 0; kt < 2; kt++) {
                    uint32_t off = (uint32_t)qrow * 80 + (uint32_t)(kt * 16 + qcol) * 2;
                    ldm_x4(qh[kt][0], qh[kt][1], qh[kt][2], qh[kt][3], qhB + off);
                }
            }

            float sc[14][4];
#pragma unroll
            for (int i = 0; i < 14; i++)
#pragma unroll
                for (int q = 0; q < 4; q++) sc[i][q] = 0.0f;

            {
                int krow = (lane & 7) + ((lane >> 4) << 3);
                int kcol = ((lane >> 3) & 1) << 3;
#pragma unroll
                for (int nt2 = 0; nt2 < 7; nt2++) {
                    int j0 = nt2 * 16;
                    uint32_t k0[4], k1[4];
                    uint32_t roff = (uint32_t)(j0 + krow) * 80;
                    ldm_x4(k0[0], k0[1], k0[2], k0[3], khB + roff + (uint32_t)(kcol) * 2);
                    ldm_x4(k1[0], k1[1], k1[2], k1[3], khB + roff + (uint32_t)(16 + kcol) * 2);
                    float* aA = sc[2 * nt2];
                    float* aB = sc[2 * nt2 + 1];
                    mma_f16(aA, qh[0], k0[0], k0[1]);
                    mma_f16(aA, qh[1], k1[0], k1[1]);
                    mma_f16(aB, qh[0], k0[2], k0[3]);
                    mma_f16(aB, qh[1], k1[2], k1[3]);
                }
            }

#pragma unroll
            for (int h2 = 0; h2 < 2; h2++) {
                int row = r0 + g + h2 * 8;
                float mx = -1e30f;
                bool rok = (row < NTOK);
#pragma unroll
                for (int i = 0; i < 14; i++) {
                    int jc = 8 * i + 2 * t;
                    float s0, s1;
                    if (rok && jc < NTOK) {
                        float2 mk = *(const float2*)(maskw + row * NTOK + jc);
                        float2 bi = *(const float2*)(biash + row * NTOK + jc);
                        s0 = sc[i][h2 * 2]     + mk.x + bi.x;
                        s1 = sc[i][h2 * 2 + 1] + mk.y + bi.y;
                    } else {
                        s0 = -1e30f; s1 = -1e30f;
                    }
                    sc[i][h2 * 2]     = s0;
                    sc[i][h2 * 2 + 1] = s1;
                    mx = fmaxf(mx, fmaxf(s0, s1));
                }
                mx = fmaxf(mx, __shfl_xor_sync(0xffffffffu, mx, 1));
                mx = fmaxf(mx, __shfl_xor_sync(0xffffffffu, mx, 2));
                float sum = 0.0f;
#pragma unroll
                for (int i = 0; i < 14; i++) {
                    float p0 = __expf(sc[i][h2 * 2]     - mx);
                    float p1 = __expf(sc[i][h2 * 2 + 1] - mx);
                    sc[i][h2 * 2]     = p0;
                    sc[i][h2 * 2 + 1] = p1;
                    sum += p0 + p1;
                }
                sum += __shfl_xor_sync(0xffffffffu, sum, 1);
                sum += __shfl_xor_sync(0xffffffffu, sum, 2);
                float inv = 1.0f / sum;
#pragma unroll
                for (int i = 0; i < 14; i++) {
                    sc[i][h2 * 2]     *= inv;
                    sc[i][h2 * 2 + 1] *= inv;
                }
            }

            float o[4][4];
#pragma unroll
            for (int n = 0; n < 4; n++)
#pragma unroll
                for (int q = 0; q < 4; q++) o[n][q] = 0.0f;

            {
                int vrow = (lane & 7) + (((lane >> 3) & 1) << 3);
                int vcol = (lane >> 4) << 3;
#pragma unroll
                for (int kk = 0; kk < 7; kk++) {
                    uint32_t ph[4];
                    {
                        __half2 p0 = __floats2half2_rn(sc[2 * kk][0],     sc[2 * kk][1]);
                        __half2 p1 = __floats2half2_rn(sc[2 * kk][2],     sc[2 * kk][3]);
                        __half2 p2 = __floats2half2_rn(sc[2 * kk + 1][0], sc[2 * kk + 1][1]);
                        __half2 p3 = __floats2half2_rn(sc[2 * kk + 1][2], sc[2 * kk + 1][3]);
                        ph[0] = *(uint32_t*)&p0;
                        ph[1] = *(uint32_t*)&p1;
                        ph[2] = *(uint32_t*)&p2;
                        ph[3] = *(uint32_t*)&p3;
                    }
                    int j0 = kk * 16;
                    uint32_t v0[4], v16[4];
                    uint32_t roff = (uint32_t)(j0 + vrow) * 80;
                    ldm_x4_t(v0[0], v0[1], v0[2], v0[3],  vhB + roff + (uint32_t)vcol * 2);
                    ldm_x4_t(v16[0], v16[1], v16[2], v16[3],
                             vhB + roff + (uint32_t)(16 + vcol) * 2);
                    mma_f16(o[0], ph, v0[0], v0[1]);
                    mma_f16(o[1], ph, v0[2], v0[3]);
                    mma_f16(o[2], ph, v16[0], v16[1]);
                    mma_f16(o[3], ph, v16[2], v16[3]);
                }
            }

            {
                int rowA = r0 + g;
                int rowB = rowA + 8;
                if (rowA < NTOK) {
                    float* dst = out + ((size_t)b * NTOK + rowA) * DIMC + h * HD;
#pragma unroll
                    for (int n = 0; n < 4; n++) {
                        float2 v = {o[n][0], o[n][1]};
                        *(float2*)(dst + n * 8 + 2 * t) = v;
                    }
                }
                if (rowB < NTOK) {
                    float* dst = out + ((size_t)b * NTOK + rowB) * DIMC + h * HD;
#pragma unroll
                    for (int n = 0; n < 4; n++) {
                        float2 v = {o[n][2], o[n][3]};
                        *(float2*)(dst + n * 8 + 2 * t) = v;
                    }
                }
            }
        }
    }
}

// ------------------------- launch ------------------------------------------

extern "C" void kernel_launch(void* const* d_in, const int* in_sizes, int n_in,
                              void* d_out, int out_size)
{
    const float* x         = (const float*)d_in[0];
    const float* mask      = (const float*)d_in[1];
    const float* qkv_w     = (const float*)d_in[2];
    const float* qkv_b     = (const float*)d_in[3];
    const float* rel_table = (const float*)d_in[4];
    const int*   rel_index = (const int*)  d_in[5];
    float* out = (float*)d_out;

    prep_all<<<(NTOT4 + 255) / 256, 256>>>(x, qkv_w, rel_table, rel_index);

    cudaFuncSetAttribute(qkv_mma, cudaFuncAttributeMaxDynamicSharedMemorySize,
                         SMEM_TOTAL);
    dim3 g1(NHEAD, GM / 128);       // (24, 196)
    qkv_mma<<<g1, 128, SMEM_TOTAL>>>(qkv_b);

    dim3 g2(NHEAD, B_ / 2);         // (24, 128) — 2 windows per CTA
    attn_tc<<<g2, 128>>>(mask, out);
}